// round 15
// baseline (speedup 1.0000x reference)
#include <cuda_runtime.h>
#include <cuda_fp16.h>
#include <math.h>
#include <stdint.h>

#define HID 4096
#define INT_DIM 16384
#define MTOK 8192
#define LN_EPS 1e-5f

// ---------------------------------------------------------------------------
// Scratch (__device__ globals: allocation-free rule)
// ---------------------------------------------------------------------------
__device__ float  g_res[(size_t)MTOK * HID];         // 128 MB fp32
__device__ __half g_ln[(size_t)MTOK * HID];          //  64 MB fp16
__device__ __half g_inter[(size_t)MTOK * INT_DIM];   // 256 MB fp16
__device__ __half g_w1t[(size_t)INT_DIM * HID];      // 128 MB  W1^T fp16
__device__ __half g_w2t[(size_t)HID * INT_DIM];      // 128 MB  W2^T fp16

__device__ __forceinline__ float gelu_tanh(float x) {
    float x3 = x * x * x;
    return 0.5f * x * (1.0f + tanhf(0.7978845608028654f * (x + 0.044715f * x3)));
}

__device__ __forceinline__ void cp16(unsigned dst, const void* src) {
    asm volatile("cp.async.cg.shared.global [%0], [%1], 16;" :: "r"(dst), "l"(src) : "memory");
}

__device__ __forceinline__ void ldsm4(unsigned& r0, unsigned& r1, unsigned& r2,
                                      unsigned& r3, unsigned addr) {
    asm volatile("ldmatrix.sync.aligned.m8n8.x4.shared.b16 {%0,%1,%2,%3}, [%4];"
                 : "=r"(r0), "=r"(r1), "=r"(r2), "=r"(r3) : "r"(addr));
}

// ---------------------------------------------------------------------------
// Kernel 1: res = input + residual + bias; ln = fp16(LN(res)*gamma + beta)
// ---------------------------------------------------------------------------
__global__ __launch_bounds__(256) void addln_kernel(
    const float* __restrict__ x, const float* __restrict__ r,
    const float* __restrict__ bias, const float* __restrict__ gamma,
    const float* __restrict__ beta)
{
    const int row = blockIdx.x;
    const int tid = threadIdx.x;
    const size_t base = (size_t)row * HID;

    float v[16];
    float sum = 0.f, sq = 0.f;
#pragma unroll
    for (int i = 0; i < 16; i++) {
        const int idx = tid + i * 256;
        const float t = x[base + idx] + r[base + idx] + bias[idx];
        v[i] = t; sum += t; sq += t * t;
    }
    __shared__ float s1[8], s2[8];
#pragma unroll
    for (int o = 16; o > 0; o >>= 1) {
        sum += __shfl_xor_sync(0xffffffffu, sum, o);
        sq  += __shfl_xor_sync(0xffffffffu, sq, o);
    }
    if ((tid & 31) == 0) { s1[tid >> 5] = sum; s2[tid >> 5] = sq; }
    __syncthreads();
    float fs = 0.f, fq = 0.f;
#pragma unroll
    for (int i = 0; i < 8; i++) { fs += s1[i]; fq += s2[i]; }
    const float mu   = fs * (1.0f / HID);
    const float var  = fq * (1.0f / HID) - mu * mu;
    const float rstd = rsqrtf(var + LN_EPS);
#pragma unroll
    for (int i = 0; i < 16; i++) {
        const int idx = tid + i * 256;
        g_res[base + idx] = v[i];
        g_ln[base + idx]  = __float2half_rn((v[i] - mu) * rstd * gamma[idx] + beta[idx]);
    }
}

// ---------------------------------------------------------------------------
// Weight prep: dst[C][R] = fp16(src[R][C])   (transpose + round)
// ---------------------------------------------------------------------------
__global__ __launch_bounds__(256) void transpose_h(
    const float* __restrict__ src, __half* __restrict__ dst, int R, int C)
{
    __shared__ float t[32][33];
    const int tx = threadIdx.x & 31, ty = threadIdx.x >> 5;
    const int x  = blockIdx.x * 32 + tx;
    const int y0 = blockIdx.y * 32 + ty;
#pragma unroll
    for (int j = 0; j < 4; j++)
        t[ty + 8 * j][tx] = src[(size_t)(y0 + 8 * j) * C + x];
    __syncthreads();
    const int x2 = blockIdx.y * 32 + tx;
    const int y2 = blockIdx.x * 32 + ty;
#pragma unroll
    for (int j = 0; j < 4; j++)
        dst[(size_t)(y2 + 8 * j) * R + x2] = __float2half_rn(t[tx][ty + 8 * j]);
}

// ---------------------------------------------------------------------------
// FP16 mma.sync m16n8k16 GEMM; cp.async 2-stage BK=128 ring; ldmatrix
// fragment pipeline primed across stage boundaries (CUTLASS multistage
// order). Half the barriers of the BK=64 version: 8 k-steps per sync.
//   C[M,Ntot] = A[M,K] @ BT[Ntot,K]^T + epilogue   (A, BT fp16; acc fp32)
//   EPI==0: C(half)  = fp16(gelu(acc + bias[n]))
//   EPI==1: C(float) = acc + resid[m,n] + bias[n]
// CTA tile 128x256x128, 8 warps (2x4), warp tile 64x64.
// Smem rows = 136 halves (272 B = 17x16B): ldmatrix chunk phases
// {0,16,...,112} mod 128 -> conflict-free; cp.async chunks 16B-aligned.
// ---------------------------------------------------------------------------
#define BM 128
#define BN 256
#define BK 128
#define ROW_H 136
#define ROW_B 272
#define STAGE_BYTES ((BM + BN) * ROW_B)           // 104448
#define NSTG 2
#define GEMM_SMEM (NSTG * STAGE_BYTES)            // 208896

template <int EPI>
__global__ __launch_bounds__(256, 1) void gemm_mma(
    const __half* __restrict__ A, const __half* __restrict__ BT,
    const float* __restrict__ bias, const float* __restrict__ resid,
    void* __restrict__ Cv, int Ntot, int K, int NT)
{
    extern __shared__ char smem[];
    const unsigned smem_u32 = (unsigned)__cvta_generic_to_shared(smem);

    const int tid  = threadIdx.x;
    const int lane = tid & 31;
    const int warp = tid >> 5;
    const int g = lane >> 2;
    const int t = lane & 3;
    const int wm = (warp >> 2) * 64;
    const int wn = (warp & 3) * 64;

    // band-of-8 raster (L2 reuse)
    const int lin  = blockIdx.x;
    const int band = lin / (8 * NT);
    const int rem  = lin - band * 8 * NT;
    const int m0   = (band * 8 + (rem & 7)) * BM;
    const int n0   = (rem >> 3) * BN;

    const int KT = K / BK;

    // ldmatrix per-lane byte offsets (stage-relative, k-step invariant)
    const int l7 = lane & 7;
    unsigned offA[4], offB[4];
#pragma unroll
    for (int mt = 0; mt < 4; mt++) {
        const int rowa = wm + mt * 16 + l7 + 8 * ((lane >> 3) & 1);
        offA[mt] = rowa * ROW_B + (((lane >> 4) & 1) * 8) * 2;
    }
#pragma unroll
    for (int p = 0; p < 4; p++) {
        const int rowb = wn + p * 16 + l7 + 8 * ((lane >> 4) & 1);
        offB[p] = BM * ROW_B + rowb * ROW_B + (((lane >> 3) & 1) * 8) * 2;
    }

    float acc[4][8][4];
#pragma unroll
    for (int i = 0; i < 4; i++)
#pragma unroll
        for (int j = 0; j < 8; j++)
#pragma unroll
            for (int k = 0; k < 4; k++) acc[i][j][k] = 0.f;

    // fragment ping-pong buffers (kept primed across stages)
    unsigned af[2][4][4], bf[2][8][2];

    auto issue_stage = [&](int slot, int kt) {
        const unsigned abase = smem_u32 + slot * STAGE_BYTES;
        const unsigned bbase = abase + BM * ROW_B;
        const int k0 = kt * BK;
#pragma unroll
        for (int i = 0; i < 8; i++) {            // A: 2048 chunks of 16B
            const int idx = tid + i * 256;
            const int r = idx >> 4, c = idx & 15;
            cp16(abase + r * ROW_B + c * 16, A + (size_t)(m0 + r) * K + k0 + c * 8);
        }
#pragma unroll
        for (int i = 0; i < 16; i++) {           // B: 4096 chunks of 16B
            const int idx = tid + i * 256;
            const int r = idx >> 4, c = idx & 15;
            cp16(bbase + r * ROW_B + c * 16, BT + (size_t)(n0 + r) * K + k0 + c * 8);
        }
    };

    auto load_frags = [&](int buf, unsigned sbase, int ks) {
        const unsigned kadd = ks * 32;           // 16 halves
#pragma unroll
        for (int mt = 0; mt < 4; mt++)
            ldsm4(af[buf][mt][0], af[buf][mt][1], af[buf][mt][2], af[buf][mt][3],
                  sbase + offA[mt] + kadd);
#pragma unroll
        for (int p = 0; p < 4; p++)
            ldsm4(bf[buf][2 * p][0], bf[buf][2 * p][1],
                  bf[buf][2 * p + 1][0], bf[buf][2 * p + 1][1],
                  sbase + offB[p] + kadd);
    };

    auto mma_step = [&](int buf) {
#pragma unroll
        for (int mt = 0; mt < 4; mt++)
#pragma unroll
            for (int nt = 0; nt < 8; nt++) {
                asm volatile(
                    "mma.sync.aligned.m16n8k16.row.col.f32.f16.f16.f32 "
                    "{%0,%1,%2,%3},{%4,%5,%6,%7},{%8,%9},{%0,%1,%2,%3};"
                    : "+f"(acc[mt][nt][0]), "+f"(acc[mt][nt][1]),
                      "+f"(acc[mt][nt][2]), "+f"(acc[mt][nt][3])
                    : "r"(af[buf][mt][0]), "r"(af[buf][mt][1]),
                      "r"(af[buf][mt][2]), "r"(af[buf][mt][3]),
                      "r"(bf[buf][nt][0]), "r"(bf[buf][nt][1]));
            }
    };

    // prologue: stage 0 in flight; wait; prime fragment pipe
    issue_stage(0, 0);
    asm volatile("cp.async.commit_group;" ::: "memory");
    asm volatile("cp.async.wait_group 0;" ::: "memory");
    __syncthreads();

    int buf = 0, slot = 0;
    load_frags(0, smem_u32, 0);                  // stage 0, ks 0

#pragma unroll 1
    for (int kt = 0; kt < KT; kt++) {
        const unsigned sbase = smem_u32 + slot * STAGE_BYTES;

        // issue next stage into the other slot (its last reader finished
        // before the barrier at the end of the previous iteration)
        if (kt + 1 < KT)
            issue_stage(slot ^ 1, kt + 1);
        asm volatile("cp.async.commit_group;" ::: "memory");

        // k-steps 0..6: prefetch next k-step, MMA current
#pragma unroll
        for (int ks = 0; ks < BK / 16 - 1; ks++) {
            load_frags(buf ^ 1, sbase, ks + 1);
            mma_step(buf);
            buf ^= 1;
        }

        // k-step 7: make next stage resident, prefetch ITS ks0, then MMA
        if (kt + 1 < KT) {
            asm volatile("cp.async.wait_group 0;" ::: "memory");
            __syncthreads();
            load_frags(buf ^ 1, smem_u32 + (slot ^ 1) * STAGE_BYTES, 0);
        }
        mma_step(buf);
        buf ^= 1;

        slot ^= 1;
    }

    // epilogue: thread owns rows wm+mt*16+g(+8), cols wn+nt*8+2t(+1)
#pragma unroll
    for (int mt = 0; mt < 4; mt++) {
#pragma unroll
        for (int nt = 0; nt < 8; nt++) {
            const int col = n0 + wn + nt * 8 + 2 * t;
#pragma unroll
            for (int h = 0; h < 2; h++) {
                const int row = m0 + wm + mt * 16 + g + h * 8;
                const size_t off = (size_t)row * Ntot + col;
                float vx = acc[mt][nt][h * 2 + 0];
                float vy = acc[mt][nt][h * 2 + 1];
                if (EPI == 0) {
                    __half2 o;
                    o.x = __float2half_rn(gelu_tanh(vx + bias[col]));
                    o.y = __float2half_rn(gelu_tanh(vy + bias[col + 1]));
                    *(__half2*)((__half*)Cv + off) = o;
                } else {
                    float2 o;
                    o.x = vx + resid[off]     + bias[col];
                    o.y = vy + resid[off + 1] + bias[col + 1];
                    *(float2*)((float*)Cv + off) = o;
                }
            }
        }
    }
}

// ---------------------------------------------------------------------------
// Launch
// ---------------------------------------------------------------------------
extern "C" void kernel_launch(void* const* d_in, const int* in_sizes, int n_in,
                              void* d_out, int out_size)
{
    const float* input     = (const float*)d_in[0];
    const float* residual  = (const float*)d_in[1];
    // d_in[2] = residual_norm: unused by the reference
    const float* attn_bias = (const float*)d_in[3];
    const float* attn_nw   = (const float*)d_in[4];
    const float* attn_nb   = (const float*)d_in[5];
    const float* inter_w   = (const float*)d_in[6];
    const float* inter_b   = (const float*)d_in[7];
    const float* output_w  = (const float*)d_in[8];
    const float* output_b  = (const float*)d_in[9];
    float* out = (float*)d_out;

    __half *ln_p, *inter_p, *w1t_p, *w2t_p;
    float *res_p;
    cudaGetSymbolAddress((void**)&ln_p, g_ln);
    cudaGetSymbolAddress((void**)&res_p, g_res);
    cudaGetSymbolAddress((void**)&inter_p, g_inter);
    cudaGetSymbolAddress((void**)&w1t_p, g_w1t);
    cudaGetSymbolAddress((void**)&w2t_p, g_w2t);

    cudaFuncSetAttribute(gemm_mma<0>, cudaFuncAttributeMaxDynamicSharedMemorySize, GEMM_SMEM);
    cudaFuncSetAttribute(gemm_mma<1>, cudaFuncAttributeMaxDynamicSharedMemorySize, GEMM_SMEM);

    // weight prep: transpose + fp16 round
    transpose_h<<<dim3(INT_DIM / 32, HID / 32), 256>>>(inter_w,  w1t_p, HID, INT_DIM);
    transpose_h<<<dim3(HID / 32, INT_DIM / 32), 256>>>(output_w, w2t_p, INT_DIM, HID);

    addln_kernel<<<MTOK, 256>>>(input, residual, attn_bias, attn_nw, attn_nb);

    // GEMM1: [8192,4096] x [4096,16384] -> g_inter (gelu, fp16)
    gemm_mma<0><<<(MTOK / BM) * (INT_DIM / BN), 256, GEMM_SMEM>>>(
        ln_p, w1t_p, inter_b, nullptr, inter_p, INT_DIM, HID, INT_DIM / BN);

    // GEMM2: [8192,16384] x [16384,4096] -> out (+res+bias, fp32)
    gemm_mma<1><<<(MTOK / BM) * (HID / BN), 256, GEMM_SMEM>>>(
        inter_p, w2t_p, output_b, res_p, out, HID, INT_DIM, HID / BN);
}

// round 16
// speedup vs baseline: 1.1916x; 1.1916x over previous
#include <cuda_runtime.h>
#include <cuda_fp16.h>
#include <math.h>
#include <stdint.h>

#define HID 4096
#define INT_DIM 16384
#define MTOK 8192
#define LN_EPS 1e-5f

// ---------------------------------------------------------------------------
// Scratch (__device__ globals: allocation-free rule)
// ---------------------------------------------------------------------------
__device__ float  g_res[(size_t)MTOK * HID];         // 128 MB fp32
__device__ __half g_ln[(size_t)MTOK * HID];          //  64 MB fp16
__device__ __half g_inter[(size_t)MTOK * INT_DIM];   // 256 MB fp16
__device__ __half g_w1t[(size_t)INT_DIM * HID];      // 128 MB  W1^T fp16
__device__ __half g_w2t[(size_t)HID * INT_DIM];      // 128 MB  W2^T fp16

__device__ __forceinline__ float gelu_tanh(float x) {
    float x3 = x * x * x;
    return 0.5f * x * (1.0f + tanhf(0.7978845608028654f * (x + 0.044715f * x3)));
}

__device__ __forceinline__ void cp16(unsigned dst, const void* src) {
    asm volatile("cp.async.cg.shared.global [%0], [%1], 16;" :: "r"(dst), "l"(src) : "memory");
}

__device__ __forceinline__ void ldsm4(unsigned& r0, unsigned& r1, unsigned& r2,
                                      unsigned& r3, unsigned addr) {
    asm volatile("ldmatrix.sync.aligned.m8n8.x4.shared.b16 {%0,%1,%2,%3}, [%4];"
                 : "=r"(r0), "=r"(r1), "=r"(r2), "=r"(r3) : "r"(addr));
}

// ---------------------------------------------------------------------------
// Kernel 1: res = input + residual + bias; ln = fp16(LN(res)*gamma + beta)
// ---------------------------------------------------------------------------
__global__ __launch_bounds__(256) void addln_kernel(
    const float* __restrict__ x, const float* __restrict__ r,
    const float* __restrict__ bias, const float* __restrict__ gamma,
    const float* __restrict__ beta)
{
    const int row = blockIdx.x;
    const int tid = threadIdx.x;
    const size_t base = (size_t)row * HID;

    float v[16];
    float sum = 0.f, sq = 0.f;
#pragma unroll
    for (int i = 0; i < 16; i++) {
        const int idx = tid + i * 256;
        const float t = x[base + idx] + r[base + idx] + bias[idx];
        v[i] = t; sum += t; sq += t * t;
    }
    __shared__ float s1[8], s2[8];
#pragma unroll
    for (int o = 16; o > 0; o >>= 1) {
        sum += __shfl_xor_sync(0xffffffffu, sum, o);
        sq  += __shfl_xor_sync(0xffffffffu, sq, o);
    }
    if ((tid & 31) == 0) { s1[tid >> 5] = sum; s2[tid >> 5] = sq; }
    __syncthreads();
    float fs = 0.f, fq = 0.f;
#pragma unroll
    for (int i = 0; i < 8; i++) { fs += s1[i]; fq += s2[i]; }
    const float mu   = fs * (1.0f / HID);
    const float var  = fq * (1.0f / HID) - mu * mu;
    const float rstd = rsqrtf(var + LN_EPS);
#pragma unroll
    for (int i = 0; i < 16; i++) {
        const int idx = tid + i * 256;
        g_res[base + idx] = v[i];
        g_ln[base + idx]  = __float2half_rn((v[i] - mu) * rstd * gamma[idx] + beta[idx]);
    }
}

// ---------------------------------------------------------------------------
// Weight prep: dst[C][R] = fp16(src[R][C])   (transpose + round)
// ---------------------------------------------------------------------------
__global__ __launch_bounds__(256) void transpose_h(
    const float* __restrict__ src, __half* __restrict__ dst, int R, int C)
{
    __shared__ float t[32][33];
    const int tx = threadIdx.x & 31, ty = threadIdx.x >> 5;
    const int x  = blockIdx.x * 32 + tx;
    const int y0 = blockIdx.y * 32 + ty;
#pragma unroll
    for (int j = 0; j < 4; j++)
        t[ty + 8 * j][tx] = src[(size_t)(y0 + 8 * j) * C + x];
    __syncthreads();
    const int x2 = blockIdx.y * 32 + tx;
    const int y2 = blockIdx.x * 32 + ty;
#pragma unroll
    for (int j = 0; j < 4; j++)
        dst[(size_t)(y2 + 8 * j) * R + x2] = __float2half_rn(t[tx][ty + 8 * j]);
}

// ---------------------------------------------------------------------------
// FP16 mma.sync m16n8k16 GEMM; cp.async 4-stage BK=64 ring (wait_group 2:
// the awaited stage was issued 3 iterations earlier -> wait ~free, only the
// barrier is exposed); ldmatrix fragment pipeline primed across stage
// boundaries (CUTLASS multistage order).
//   C[M,Ntot] = A[M,K] @ BT[Ntot,K]^T + epilogue   (A, BT fp16; acc fp32)
//   EPI==0: C(half)  = fp16(gelu(acc + bias[n]))
//   EPI==1: C(float) = acc + resid[m,n] + bias[n]
// CTA tile 128x256x64, 8 warps (2x4), warp tile 64x64.
// Smem rows = 72 halves (144 B): ldmatrix chunk phases conflict-free;
// cp.async chunks 16B-aligned (144 = 9*16).
// ---------------------------------------------------------------------------
#define BM 128
#define BN 256
#define BK 64
#define ROW_H 72
#define ROW_B 144
#define STAGE_BYTES ((BM + BN) * ROW_B)           // 55296
#define NSTG 4
#define GEMM_SMEM (NSTG * STAGE_BYTES)            // 221184

template <int EPI>
__global__ __launch_bounds__(256, 1) void gemm_mma(
    const __half* __restrict__ A, const __half* __restrict__ BT,
    const float* __restrict__ bias, const float* __restrict__ resid,
    void* __restrict__ Cv, int Ntot, int K, int NT)
{
    extern __shared__ char smem[];
    const unsigned smem_u32 = (unsigned)__cvta_generic_to_shared(smem);

    const int tid  = threadIdx.x;
    const int lane = tid & 31;
    const int warp = tid >> 5;
    const int g = lane >> 2;
    const int t = lane & 3;
    const int wm = (warp >> 2) * 64;
    const int wn = (warp & 3) * 64;

    // band-of-8 raster (L2 reuse)
    const int lin  = blockIdx.x;
    const int band = lin / (8 * NT);
    const int rem  = lin - band * 8 * NT;
    const int m0   = (band * 8 + (rem & 7)) * BM;
    const int n0   = (rem >> 3) * BN;

    const int KT = K / BK;

    // ldmatrix per-lane byte offsets (stage-relative, k-step invariant)
    const int l7 = lane & 7;
    unsigned offA[4], offB[4];
#pragma unroll
    for (int mt = 0; mt < 4; mt++) {
        const int rowa = wm + mt * 16 + l7 + 8 * ((lane >> 3) & 1);
        offA[mt] = rowa * ROW_B + (((lane >> 4) & 1) * 8) * 2;
    }
#pragma unroll
    for (int p = 0; p < 4; p++) {
        const int rowb = wn + p * 16 + l7 + 8 * ((lane >> 4) & 1);
        offB[p] = BM * ROW_B + rowb * ROW_B + (((lane >> 3) & 1) * 8) * 2;
    }

    float acc[4][8][4];
#pragma unroll
    for (int i = 0; i < 4; i++)
#pragma unroll
        for (int j = 0; j < 8; j++)
#pragma unroll
            for (int k = 0; k < 4; k++) acc[i][j][k] = 0.f;

    // fragment ping-pong buffers (kept primed across stages)
    unsigned af[2][4][4], bf[2][8][2];

    auto issue_stage = [&](int slot, int kt) {
        const unsigned abase = smem_u32 + slot * STAGE_BYTES;
        const unsigned bbase = abase + BM * ROW_B;
        const int k0 = kt * BK;
#pragma unroll
        for (int i = 0; i < 4; i++) {            // A: 1024 chunks
            const int idx = tid + i * 256;
            const int r = idx >> 3, c = idx & 7;
            cp16(abase + r * ROW_B + c * 16, A + (size_t)(m0 + r) * K + k0 + c * 8);
        }
#pragma unroll
        for (int i = 0; i < 8; i++) {            // B: 2048 chunks
            const int idx = tid + i * 256;
            const int r = idx >> 3, c = idx & 7;
            cp16(bbase + r * ROW_B + c * 16, BT + (size_t)(n0 + r) * K + k0 + c * 8);
        }
    };

    auto load_frags = [&](int buf, unsigned sbase, int ks) {
        const unsigned kadd = ks * 32;           // 16 halves
#pragma unroll
        for (int mt = 0; mt < 4; mt++)
            ldsm4(af[buf][mt][0], af[buf][mt][1], af[buf][mt][2], af[buf][mt][3],
                  sbase + offA[mt] + kadd);
#pragma unroll
        for (int p = 0; p < 4; p++)
            ldsm4(bf[buf][2 * p][0], bf[buf][2 * p][1],
                  bf[buf][2 * p + 1][0], bf[buf][2 * p + 1][1],
                  sbase + offB[p] + kadd);
    };

    auto mma_step = [&](int buf) {
#pragma unroll
        for (int mt = 0; mt < 4; mt++)
#pragma unroll
            for (int nt = 0; nt < 8; nt++) {
                asm volatile(
                    "mma.sync.aligned.m16n8k16.row.col.f32.f16.f16.f32 "
                    "{%0,%1,%2,%3},{%4,%5,%6,%7},{%8,%9},{%0,%1,%2,%3};"
                    : "+f"(acc[mt][nt][0]), "+f"(acc[mt][nt][1]),
                      "+f"(acc[mt][nt][2]), "+f"(acc[mt][nt][3])
                    : "r"(af[buf][mt][0]), "r"(af[buf][mt][1]),
                      "r"(af[buf][mt][2]), "r"(af[buf][mt][3]),
                      "r"(bf[buf][nt][0]), "r"(bf[buf][nt][1]));
            }
    };

    // prologue: stages 0,1,2 in flight; wait stage 0; prime fragment pipe
    issue_stage(0, 0);
    asm volatile("cp.async.commit_group;" ::: "memory");
    issue_stage(1, 1);
    asm volatile("cp.async.commit_group;" ::: "memory");
    issue_stage(2, 2);
    asm volatile("cp.async.commit_group;" ::: "memory");
    asm volatile("cp.async.wait_group 2;" ::: "memory");
    __syncthreads();

    int buf = 0, slot = 0;
    load_frags(0, smem_u32, 0);                  // stage 0, ks 0

#pragma unroll 1
    for (int kt = 0; kt < KT; kt++) {
        const unsigned sbase = smem_u32 + slot * STAGE_BYTES;

        // issue stage kt+3 (slot = kt-1 mod 4: its last LDSM read happened
        // before the barrier at the end of the previous iteration). Always
        // commit (empty group at tail keeps wait_group accounting exact).
        if (kt + 3 < KT) {
            int ns = slot + 3; if (ns >= NSTG) ns -= NSTG;
            issue_stage(ns, kt + 3);
        }
        asm volatile("cp.async.commit_group;" ::: "memory");

        // k-steps 0..2: prefetch next k-step, MMA current
#pragma unroll
        for (int ks = 0; ks < BK / 16 - 1; ks++) {
            load_frags(buf ^ 1, sbase, ks + 1);
            mma_step(buf);
            buf ^= 1;
        }

        // k-step 3: make next stage resident (deep slack: issued 3 iters
        // ago, wait ~free), prefetch ITS ks0, then MMA
        if (kt + 1 < KT) {
            asm volatile("cp.async.wait_group 2;" ::: "memory");
            __syncthreads();
            int ns = slot + 1; if (ns >= NSTG) ns -= NSTG;
            load_frags(buf ^ 1, smem_u32 + ns * STAGE_BYTES, 0);
        }
        mma_step(buf);
        buf ^= 1;

        if (++slot == NSTG) slot = 0;
    }

    // epilogue: thread owns rows wm+mt*16+g(+8), cols wn+nt*8+2t(+1)
#pragma unroll
    for (int mt = 0; mt < 4; mt++) {
#pragma unroll
        for (int nt = 0; nt < 8; nt++) {
            const int col = n0 + wn + nt * 8 + 2 * t;
#pragma unroll
            for (int h = 0; h < 2; h++) {
                const int row = m0 + wm + mt * 16 + g + h * 8;
                const size_t off = (size_t)row * Ntot + col;
                float vx = acc[mt][nt][h * 2 + 0];
                float vy = acc[mt][nt][h * 2 + 1];
                if (EPI == 0) {
                    __half2 o;
                    o.x = __float2half_rn(gelu_tanh(vx + bias[col]));
                    o.y = __float2half_rn(gelu_tanh(vy + bias[col + 1]));
                    *(__half2*)((__half*)Cv + off) = o;
                } else {
                    float2 o;
                    o.x = vx + resid[off]     + bias[col];
                    o.y = vy + resid[off + 1] + bias[col + 1];
                    *(float2*)((float*)Cv + off) = o;
                }
            }
        }
    }
}

// ---------------------------------------------------------------------------
// Launch
// ---------------------------------------------------------------------------
extern "C" void kernel_launch(void* const* d_in, const int* in_sizes, int n_in,
                              void* d_out, int out_size)
{
    const float* input     = (const float*)d_in[0];
    const float* residual  = (const float*)d_in[1];
    // d_in[2] = residual_norm: unused by the reference
    const float* attn_bias = (const float*)d_in[3];
    const float* attn_nw   = (const float*)d_in[4];
    const float* attn_nb   = (const float*)d_in[5];
    const float* inter_w   = (const float*)d_in[6];
    const float* inter_b   = (const float*)d_in[7];
    const float* output_w  = (const float*)d_in[8];
    const float* output_b  = (const float*)d_in[9];
    float* out = (float*)d_out;

    __half *ln_p, *inter_p, *w1t_p, *w2t_p;
    float *res_p;
    cudaGetSymbolAddress((void**)&ln_p, g_ln);
    cudaGetSymbolAddress((void**)&res_p, g_res);
    cudaGetSymbolAddress((void**)&inter_p, g_inter);
    cudaGetSymbolAddress((void**)&w1t_p, g_w1t);
    cudaGetSymbolAddress((void**)&w2t_p, g_w2t);

    cudaFuncSetAttribute(gemm_mma<0>, cudaFuncAttributeMaxDynamicSharedMemorySize, GEMM_SMEM);
    cudaFuncSetAttribute(gemm_mma<1>, cudaFuncAttributeMaxDynamicSharedMemorySize, GEMM_SMEM);

    // weight prep: transpose + fp16 round
    transpose_h<<<dim3(INT_DIM / 32, HID / 32), 256>>>(inter_w,  w1t_p, HID, INT_DIM);
    transpose_h<<<dim3(HID / 32, INT_DIM / 32), 256>>>(output_w, w2t_p, INT_DIM, HID);

    addln_kernel<<<MTOK, 256>>>(input, residual, attn_bias, attn_nw, attn_nb);

    // GEMM1: [8192,4096] x [4096,16384] -> g_inter (gelu, fp16)
    gemm_mma<0><<<(MTOK / BM) * (INT_DIM / BN), 256, GEMM_SMEM>>>(
        ln_p, w1t_p, inter_b, nullptr, inter_p, INT_DIM, HID, INT_DIM / BN);

    // GEMM2: [8192,16384] x [16384,4096] -> out (+res+bias, fp32)
    gemm_mma<1><<<(MTOK / BM) * (HID / BN), 256, GEMM_SMEM>>>(
        inter_p, w2t_p, output_b, res_p, out, HID, INT_DIM, HID / BN);
}